// round 8
// baseline (speedup 1.0000x reference)
#include <cuda_runtime.h>

#define NTOT 50000
#define AANCH 32
#define DDIM 64
#define NG 3125                      // NTOT/16
#define UBLK 2                       // u's per prep G-block
#define NBG2 ((NG + UBLK - 1) / UBLK)   // 1563
#define MROWS 64                     // rows per main block

// plain C: g_C[a*64+k] = (1/32) * embeds[anchor[a]] . W1[k,:]
__device__ __align__(16) float g_C[AANCH * DDIM];
// pair-G: g_G2[u*64+k] = (E16[u]+E16[(u+1)%NG]).W2[k,:]/32 + b[k]
__device__ __align__(16) float g_G2[NG * DDIM];

typedef unsigned long long u64;
union F4U { float4 f; u64 u[2]; };

__device__ __forceinline__ void unpack2(u64 v, float& x, float& y) {
    asm("mov.b64 {%0,%1}, %2;" : "=f"(x), "=f"(y) : "l"(v));
}
__device__ __forceinline__ u64 fma2(u64 a, u64 b, u64 c) {
    u64 d; asm("fma.rn.f32x2 %0, %1, %2, %3;" : "=l"(d) : "l"(a), "l"(b), "l"(c)); return d;
}

// ---------------------------------------------------------------------------
// prep: bid 0 -> anchor projections (g_C). bid 1..NBG2 -> 2 G2 rows each.
// 128 threads.
// ---------------------------------------------------------------------------
__global__ __launch_bounds__(128) void prep_kernel(
    const float* __restrict__ embeds,
    const int* __restrict__ anchor,
    const float* __restrict__ Wh,
    const float* __restrict__ bias)
{
    __shared__ float Wt[DDIM * 65];      // G: W2t[d*65+k]  |  anchors: Es[a*65+d]
    __shared__ float Ps[12 * DDIM];      // 4-row partial sums
    __shared__ float E32[2 * DDIM];
    const int t = threadIdx.x;

    if (blockIdx.x == 0) {
        // ---- anchor projections -> g_C (runs first, overlaps the grid)
        float* Es = Wt;                  // [32][65]
        #pragma unroll
        for (int i = 0; i < 4; i++) {    // 512 float4 tasks
            int idx = t + i * 128;
            int a = idx >> 4, c = idx & 15;
            float4 v = *(const float4*)(embeds + (size_t)anchor[a] * DDIM + 4 * c);
            Es[a * 65 + 4 * c + 0] = v.x;
            Es[a * 65 + 4 * c + 1] = v.y;
            Es[a * 65 + 4 * c + 2] = v.z;
            Es[a * 65 + 4 * c + 3] = v.w;
        }
        __syncthreads();
        int ia = t >> 2;                 // 0..31
        int kg = t & 3;                  // k = kg*16 + kk
        #pragma unroll
        for (int kk = 0; kk < 16; kk++) {
            int k = kg * 16 + kk;
            const float* w = Wh + k * 2 * DDIM;      // W1 row k
            float s = 0.f;
            #pragma unroll 16
            for (int d = 0; d < DDIM; d++)
                s += Es[ia * 65 + d] * __ldg(w + d);
            g_C[ia * DDIM + k] = s * (1.0f / 32.0f);
        }
        return;
    }

    // ---- G path
    const int u0 = (blockIdx.x - 1) * UBLK;
    // stage W2 transposed: Wt[d*65+k] = Wh[k*128+64+d]  (1024 float4 tasks)
    #pragma unroll
    for (int i = 0; i < 8; i++) {
        int idx = t + i * 128;
        int k = idx >> 4, dq = idx & 15;
        float4 v = *(const float4*)(Wh + k * 2 * DDIM + DDIM + 4 * dq);
        Wt[(4 * dq + 0) * 65 + k] = v.x;
        Wt[(4 * dq + 1) * 65 + k] = v.y;
        Wt[(4 * dq + 2) * 65 + k] = v.z;
        Wt[(4 * dq + 3) * 65 + k] = v.w;
    }
    // phase A: 192 tasks of 4-row float4 partial sums (rows 16u0 .. 16u0+47)
    #pragma unroll
    for (int i = 0; i < 2; i++) {
        int idx = t + i * 128;
        if (idx < 192) {
            int p = idx >> 4, c = idx & 15;
            int row = 16 * u0 + 4 * p;
            if (row >= NTOT) row -= NTOT;            // wrap (N % 4 == 0, no straddle)
            const float4* src = (const float4*)(embeds + (size_t)row * DDIM) + c;
            float4 a = make_float4(0.f, 0.f, 0.f, 0.f);
            #pragma unroll
            for (int j = 0; j < 4; j++) {
                float4 v = src[j * 16];
                a.x += v.x; a.y += v.y; a.z += v.z; a.w += v.w;
            }
            ((float4*)Ps)[p * 16 + c] = a;
        }
    }
    __syncthreads();
    // phase B: E32[uu][d] = sum of partials 4uu .. 4uu+7  (128 tasks)
    {
        int uu = t >> 6, d = t & 63;
        float s = 0.f;
        #pragma unroll
        for (int p = 0; p < 8; p++) s += Ps[(4 * uu + p) * DDIM + d];
        E32[uu * DDIM + d] = s;
    }
    __syncthreads();
    // phase C: one output per thread
    {
        int k = t & 63, uu = t >> 6;
        int u = u0 + uu;
        float s = 0.f;
        #pragma unroll 16
        for (int d = 0; d < DDIM; d++)
            s += E32[uu * DDIM + d] * Wt[d * 65 + k];    // broadcast x stride-1
        if (u < NG)
            g_G2[u * DDIM + k] = s * (1.0f / 32.0f) + __ldg(bias + k);
    }
}

// ---------------------------------------------------------------------------
// main: block = 64 rows x 64 cols, 128 threads; warp = 64 rows x 16 cols.
// dists staged DUPLICATED in smem -> pure-LDS mainloop (no LDG, no pack).
// out[n,k] = sum_a dists[a,n]*C[a,k] + G2[(2n)%NG, k]
// ---------------------------------------------------------------------------
__global__ __launch_bounds__(128) void main_kernel(
    const float* __restrict__ dists,
    float* __restrict__ out)
{
    __shared__ __align__(16) float smem[AANCH * 2 * MROWS + AANCH * DDIM]; // 24KB
    float* Xd = smem;                         // [32][128] dup: Xd[a][2r]=Xd[a][2r+1]
    float* Cs = smem + AANCH * 2 * MROWS;     // [32][64] plain C
    float* Os = smem;                         // epilogue alias: [64][65] (16.6KB)
    const int t = threadIdx.x;
    const int lane = t & 31;
    const int wid = t >> 5;
    const int c0 = wid * 16;
    const int rowbase = blockIdx.x * MROWS;

    // stage C (8 KB, L2-resident)
    {
        float4* dst = (float4*)Cs;
        const float4* src = (const float4*)g_C;
        #pragma unroll
        for (int i = 0; i < 4; i++)
            dst[t + i * 128] = src[t + i * 128];
    }
    // stage dists duplicated
    if (rowbase + MROWS <= NTOT) {
        #pragma unroll
        for (int i = 0; i < 4; i++) {             // 512 float4 src tasks
            int idx = t + i * 128;
            int a = idx >> 4, c = idx & 15;
            float4 v = *(const float4*)(dists + (size_t)a * NTOT + rowbase + 4 * c);
            float4* dst = (float4*)(Xd + a * 128 + 8 * c);
            dst[0] = make_float4(v.x, v.x, v.y, v.y);
            dst[1] = make_float4(v.z, v.z, v.w, v.w);
        }
    } else {
        #pragma unroll
        for (int i = 0; i < 16; i++) {            // scalar clamp path (tail block)
            int idx = t + i * 128;
            int a = idx >> 6, r = idx & 63;
            int row = rowbase + r; if (row >= NTOT) row = NTOT - 1;
            float v = dists[(size_t)a * NTOT + row];
            Xd[a * 128 + 2 * r]     = v;
            Xd[a * 128 + 2 * r + 1] = v;
        }
    }
    __syncthreads();

    u64 acc0[8], acc1[8];
    #pragma unroll
    for (int q = 0; q < 8; q++) { acc0[q] = 0ULL; acc1[q] = 0ULL; }

    const float* xb = Xd + 2 * lane;
    const float4* Crow = (const float4*)Cs + (c0 >> 2);
    #pragma unroll
    for (int a = 0; a < AANCH; a++) {
        u64 b0 = *(const u64*)(xb + a * 128);          // (d_r0, d_r0)
        u64 b1 = *(const u64*)(xb + a * 128 + 64);     // (d_r1, d_r1)
        #pragma unroll
        for (int qq = 0; qq < 4; qq++) {
            F4U cu; cu.f = Crow[a * 16 + qq];          // broadcast LDS.128
            acc0[2 * qq]     = fma2(b0, cu.u[0], acc0[2 * qq]);
            acc0[2 * qq + 1] = fma2(b0, cu.u[1], acc0[2 * qq + 1]);
            acc1[2 * qq]     = fma2(b1, cu.u[0], acc1[2 * qq]);
            acc1[2 * qq + 1] = fma2(b1, cu.u[1], acc1[2 * qq + 1]);
        }
    }
    __syncthreads();      // Xd/Cs dead, alias as Os

    // transpose tile: scalar STS stride 65 (conflict-free)
    #pragma unroll
    for (int qq = 0; qq < 8; qq++) {
        float x, y;
        unpack2(acc0[qq], x, y);
        Os[lane * 65 + c0 + 2 * qq]     = x;
        Os[lane * 65 + c0 + 2 * qq + 1] = y;
        unpack2(acc1[qq], x, y);
        Os[(32 + lane) * 65 + c0 + 2 * qq]     = x;
        Os[(32 + lane) * 65 + c0 + 2 * qq + 1] = y;
    }
    __syncthreads();

    // fused G2 add + coalesced store
    const int rows_valid = NTOT - rowbase;
    const int k = t & 63;
    int r = t >> 6;
    int u1 = (2 * (rowbase + r)) % NG;
    #pragma unroll 8
    for (int i = 0; i < MROWS / 2; i++, r += 2) {
        if (r < rows_valid) {
            float g = __ldg(g_G2 + (size_t)u1 * DDIM + k);   // L2-resident
            out[(size_t)(rowbase + r) * DDIM + k] = Os[r * 65 + k] + g;
        }
        u1 += 4; if (u1 >= NG) u1 -= NG;
    }
}

// ---------------------------------------------------------------------------
extern "C" void kernel_launch(void* const* d_in, const int* in_sizes, int n_in,
                              void* d_out, int out_size)
{
    const float* embeds = (const float*)d_in[0];   // (N, D)
    const float* dists  = (const float*)d_in[1];   // (A, N)
    const int*   anchor = (const int*)d_in[2];     // (A,)
    const float* Wh     = (const float*)d_in[3];   // (D, 2D)
    const float* bias   = (const float*)d_in[4];   // (D,)
    float* out = (float*)d_out;
    (void)in_sizes; (void)n_in; (void)out_size;

    prep_kernel<<<NBG2 + 1, 128>>>(embeds, anchor, Wh, bias);
    main_kernel<<<(NTOT + MROWS - 1) / MROWS, 128>>>(dists, out);
}

// round 9
// speedup vs baseline: 1.4987x; 1.4987x over previous
#include <cuda_runtime.h>

#define NTOT 50000
#define AANCH 32
#define DDIM 64
#define NG 3125                      // NTOT/16
#define UB 8                         // u's per prep G-block
#define NBG ((NG + UB - 1) / UB)     // 391
#define MROWS 64                     // rows per main block

// plain C: g_C[a*64+k] = (1/32) * embeds[anchor[a]] . W1[k,:]
__device__ __align__(16) float g_C[AANCH * DDIM];
// pair-G: g_G2[u*64+k] = (E16[u]+E16[(u+1)%NG]).W2[k,:]/32 + b[k]
__device__ __align__(16) float g_G2[NG * DDIM];

typedef unsigned long long u64;
union F4U { float4 f; u64 u[2]; };

__device__ __forceinline__ u64 pack2(float x, float y) {
    u64 r; asm("mov.b64 %0, {%1,%2};" : "=l"(r) : "f"(x), "f"(y)); return r;
}
__device__ __forceinline__ void unpack2(u64 v, float& x, float& y) {
    asm("mov.b64 {%0,%1}, %2;" : "=f"(x), "=f"(y) : "l"(v));
}
__device__ __forceinline__ u64 fma2(u64 a, u64 b, u64 c) {
    u64 d; asm("fma.rn.f32x2 %0, %1, %2, %3;" : "=l"(d) : "l"(a), "l"(b), "l"(c)); return d;
}

// ---------------------------------------------------------------------------
// prep: bid 0 -> anchor projections (g_C). bid 1..NBG: 8 G2 rows each
// (E16 computed in-block incl. the u0+8 neighbor, with wrap). 256 threads.
// ---------------------------------------------------------------------------
__global__ __launch_bounds__(256) void prep_kernel(
    const float* __restrict__ embeds,
    const int* __restrict__ anchor,
    const float* __restrict__ Wh,
    const float* __restrict__ bias)
{
    __shared__ float Wt[DDIM * 65];   // G path: W2t[d*65+k]. anchor path: W1[k*65+d]
    __shared__ float Buf[2080];       // G: Ps[18][64] + E32[8][64] | anchors: Es[32][65]
    const int t = threadIdx.x;

    if (blockIdx.x == 0) {
        // ---- anchor projections -> g_C
        #pragma unroll
        for (int i = 0; i < 16; i++) {
            int idx = t + i * 256;
            int k = idx >> 6, d = idx & 63;
            Wt[k * 65 + d] = Wh[k * 2 * DDIM + d];             // W1[k][d]
        }
        float* Es = Buf;                                       // [32][65]
        #pragma unroll
        for (int i = 0; i < 8; i++) {
            int idx = t + i * 256;
            int a = idx >> 6, d = idx & 63;
            Es[a * 65 + d] = embeds[(size_t)anchor[a] * DDIM + d];
        }
        __syncthreads();
        int ia = t >> 3;
        int kbase = (t & 7) * 8;
        float s[8];
        #pragma unroll
        for (int kk = 0; kk < 8; kk++) s[kk] = 0.f;
        #pragma unroll 8
        for (int d = 0; d < DDIM; d++) {
            float e = Es[ia * 65 + d];
            #pragma unroll
            for (int kk = 0; kk < 8; kk++) s[kk] += e * Wt[(kbase + kk) * 65 + d];
        }
        #pragma unroll
        for (int kk = 0; kk < 8; kk++)
            g_C[ia * DDIM + kbase + kk] = s[kk] * (1.0f / 32.0f);
        return;
    }

    // ---- G path
    const int u0 = (blockIdx.x - 1) * UB;
    // stage W2 transposed: Wt[d*65+k] = Wh[k*128+64+d]
    #pragma unroll
    for (int i = 0; i < 4; i++) {
        int idx = t + i * 256;            // 1024 float4 tasks
        int k = idx >> 4, dq = idx & 15;
        float4 v = *(const float4*)(Wh + k * 2 * DDIM + DDIM + 4 * dq);
        Wt[(4 * dq + 0) * 65 + k] = v.x;
        Wt[(4 * dq + 1) * 65 + k] = v.y;
        Wt[(4 * dq + 2) * 65 + k] = v.z;
        Wt[(4 * dq + 3) * 65 + k] = v.w;
    }
    // phase A: 288 tasks of 8-row float4 partial sums (u's u0..u0+8)
    float* Ps = Buf;                      // [18][64]
    for (int s = t; s < (UB + 1) * 32; s += 256) {
        int uu = s >> 5, h = (s >> 4) & 1, c = s & 15;
        int rb = 16 * (u0 + uu);
        if (rb >= NTOT) rb -= NTOT;       // wrap (u = NG neighbor and guard rows)
        const float4* src = (const float4*)(embeds + (size_t)(rb + 8 * h) * DDIM) + c;
        float4 a = make_float4(0.f, 0.f, 0.f, 0.f);
        #pragma unroll
        for (int j = 0; j < 8; j++) {
            float4 v = src[j * 16];
            a.x += v.x; a.y += v.y; a.z += v.z; a.w += v.w;
        }
        float* dst = Ps + (uu * 2 + h) * DDIM + 4 * c;
        dst[0] = a.x; dst[1] = a.y; dst[2] = a.z; dst[3] = a.w;
    }
    __syncthreads();
    // phase B: E32[uu][d] = Ps[2uu]+Ps[2uu+1]+Ps[2uu+2]+Ps[2uu+3]  (512 tasks)
    float* E32 = Buf + 18 * DDIM;         // [8][64]
    #pragma unroll
    for (int i = 0; i < 2; i++) {
        int s = t + i * 256;
        int uu = s >> 6, d = s & 63;
        E32[uu * DDIM + d] =
            Ps[(2 * uu) * DDIM + d] + Ps[(2 * uu + 1) * DDIM + d] +
            Ps[(2 * uu + 2) * DDIM + d] + Ps[(2 * uu + 3) * DDIM + d];
    }
    __syncthreads();
    // phase C: 2 outputs/thread
    {
        int k = t & 63;
        int uu0 = t >> 6;                 // 0..3
        float b = __ldg(bias + k);
        #pragma unroll
        for (int ii = 0; ii < 2; ii++) {
            int uu = uu0 + 4 * ii;
            int u = u0 + uu;
            float s = 0.f;
            #pragma unroll 16
            for (int d = 0; d < DDIM; d++)
                s += E32[uu * DDIM + d] * Wt[d * 65 + k];   // broadcast x stride-1
            if (u < NG)
                g_G2[u * DDIM + k] = s * (1.0f / 32.0f) + b;
        }
    }
}

// ---------------------------------------------------------------------------
// main (R7 structure + G2 prefetch + PDL wait):
// block = 64 rows x 64 cols, 128 threads; warp = 64 rows x 16 cols.
// out[n,k] = sum_a dists[a,n]*C[a,k] + G2[(2n)%NG, k]
// ---------------------------------------------------------------------------
__global__ __launch_bounds__(128) void main_kernel(
    const float* __restrict__ dists,
    float* __restrict__ out)
{
    __shared__ __align__(16) float Cs[AANCH * DDIM];   // 8 KB
    __shared__ __align__(16) float Os[MROWS * 65];     // 16.25 KB
    const int t = threadIdx.x;
    const int lane = t & 31;
    const int wid = t >> 5;
    const int c0 = wid * 16;
    const int rowbase = blockIdx.x * MROWS;

    int n0 = rowbase + lane;      if (n0 >= NTOT) n0 = NTOT - 1;
    int n1 = rowbase + 32 + lane; if (n1 >= NTOT) n1 = NTOT - 1;

    // prep-independent DRAM loads issued first (overlap the PDL wait)
    float dv0[32], dv1[32];
    #pragma unroll
    for (int a = 0; a < 32; a++) dv0[a] = __ldg(dists + (size_t)a * NTOT + n0);
    #pragma unroll
    for (int a = 0; a < 32; a++) dv1[a] = __ldg(dists + (size_t)a * NTOT + n1);

    // wait for prep grid's writes (g_C, g_G2) to be visible
    asm volatile("griddepcontrol.wait;" ::: "memory");

    {   // stage C
        float4* dst = (float4*)Cs;
        const float4* src = (const float4*)g_C;
        #pragma unroll
        for (int i = 0; i < 4; i++)
            dst[t + i * 128] = src[t + i * 128];
    }
    __syncthreads();

    u64 acc0[8], acc1[8];
    #pragma unroll
    for (int q = 0; q < 8; q++) { acc0[q] = 0ULL; acc1[q] = 0ULL; }

    const float4* Crow = (const float4*)Cs + (c0 >> 2);
    #pragma unroll
    for (int a = 0; a < 32; a++) {
        u64 b0 = pack2(dv0[a], dv0[a]);
        u64 b1 = pack2(dv1[a], dv1[a]);
        #pragma unroll
        for (int qq = 0; qq < 4; qq++) {
            F4U cu; cu.f = Crow[a * 16 + qq];              // broadcast LDS.128
            acc0[2 * qq]     = fma2(b0, cu.u[0], acc0[2 * qq]);
            acc0[2 * qq + 1] = fma2(b0, cu.u[1], acc0[2 * qq + 1]);
            acc1[2 * qq]     = fma2(b1, cu.u[0], acc1[2 * qq]);
            acc1[2 * qq + 1] = fma2(b1, cu.u[1], acc1[2 * qq + 1]);
        }
    }

    // prefetch all 32 G2 values for this thread's epilogue (MLP=32, latency
    // hidden behind the transpose STS + barrier below)
    const int k = t & 63;
    float gpre[32];
    {
        int r = t >> 6;
        int u1 = (2 * (rowbase + r)) % NG;
        #pragma unroll
        for (int i = 0; i < MROWS / 2; i++) {
            gpre[i] = __ldg(g_G2 + (size_t)u1 * DDIM + k);
            u1 += 4; if (u1 >= NG) u1 -= NG;
        }
    }

    // block transpose tile, scalar STS stride 65 (conflict-free)
    #pragma unroll
    for (int qq = 0; qq < 8; qq++) {
        float x, y;
        unpack2(acc0[qq], x, y);
        Os[lane * 65 + c0 + 2 * qq]     = x;
        Os[lane * 65 + c0 + 2 * qq + 1] = y;
        unpack2(acc1[qq], x, y);
        Os[(32 + lane) * 65 + c0 + 2 * qq]     = x;
        Os[(32 + lane) * 65 + c0 + 2 * qq + 1] = y;
    }
    __syncthreads();

    // fused add + coalesced store (no in-loop global loads)
    const int rows_valid = NTOT - rowbase;
    int r = t >> 6;
    #pragma unroll 8
    for (int i = 0; i < MROWS / 2; i++, r += 2) {
        if (r < rows_valid)
            out[(size_t)(rowbase + r) * DDIM + k] = Os[r * 65 + k] + gpre[i];
    }
}

// ---------------------------------------------------------------------------
extern "C" void kernel_launch(void* const* d_in, const int* in_sizes, int n_in,
                              void* d_out, int out_size)
{
    const float* embeds = (const float*)d_in[0];   // (N, D)
    const float* dists  = (const float*)d_in[1];   // (A, N)
    const int*   anchor = (const int*)d_in[2];     // (A,)
    const float* Wh     = (const float*)d_in[3];   // (D, 2D)
    const float* bias   = (const float*)d_in[4];   // (D,)
    float* out = (float*)d_out;
    (void)in_sizes; (void)n_in; (void)out_size;

    prep_kernel<<<NBG + 1, 256>>>(embeds, anchor, Wh, bias);

    // main with programmatic dependent launch: overlaps its launch + dists
    // prefix with prep's tail; griddepcontrol.wait guards g_C/g_G2 reads.
    cudaLaunchConfig_t cfg = {};
    cfg.gridDim  = dim3((NTOT + MROWS - 1) / MROWS);   // 782
    cfg.blockDim = dim3(128);
    cudaLaunchAttribute attr[1];
    attr[0].id = cudaLaunchAttributeProgrammaticStreamSerialization;
    attr[0].val.programmaticStreamSerializationAllowed = 1;
    cfg.attrs = attr;
    cfg.numAttrs = 1;
    cudaLaunchKernelEx(&cfg, main_kernel, dists, out);
}

// round 10
// speedup vs baseline: 1.6162x; 1.0784x over previous
#include <cuda_runtime.h>

#define NTOT 50000
#define AANCH 32
#define DDIM 64
#define NG 3125                      // NTOT/16
#define UB 8                         // u's per prep G-block
#define NBG ((NG + UB - 1) / UB)     // 391
#define MROWS 64                     // rows per main block

// plain C: g_C[a*64+k] = (1/32) * embeds[anchor[a]] . W1[k,:]
__device__ __align__(16) float g_C[AANCH * DDIM];
// pair-G: g_G2[u*64+k] = (E16[u]+E16[(u+1)%NG]).W2[k,:]/32 + b[k]
__device__ __align__(16) float g_G2[NG * DDIM];

typedef unsigned long long u64;
union F4U { float4 f; u64 u[2]; };

__device__ __forceinline__ u64 pack2(float x, float y) {
    u64 r; asm("mov.b64 %0, {%1,%2};" : "=l"(r) : "f"(x), "f"(y)); return r;
}
__device__ __forceinline__ void unpack2(u64 v, float& x, float& y) {
    asm("mov.b64 {%0,%1}, %2;" : "=f"(x), "=f"(y) : "l"(v));
}
__device__ __forceinline__ u64 fma2(u64 a, u64 b, u64 c) {
    u64 d; asm("fma.rn.f32x2 %0, %1, %2, %3;" : "=l"(d) : "l"(a), "l"(b), "l"(c)); return d;
}
// non-sinkable global load: forces issue HERE, result pinned in a register
__device__ __forceinline__ float ldg_force(const float* p) {
    float v; asm volatile("ld.global.nc.f32 %0, [%1];" : "=f"(v) : "l"(p)); return v;
}

// ---------------------------------------------------------------------------
// prep: bid 0 -> anchor projections (g_C). bid 1..NBG: 8 G2 rows each
// (E16 computed in-block incl. the u0+8 neighbor, with wrap). 256 threads.
// ---------------------------------------------------------------------------
__global__ __launch_bounds__(256) void prep_kernel(
    const float* __restrict__ embeds,
    const int* __restrict__ anchor,
    const float* __restrict__ Wh,
    const float* __restrict__ bias)
{
    __shared__ float Wt[DDIM * 65];   // G path: W2t[d*65+k]. anchor path: W1[k*65+d]
    __shared__ float Buf[2080];       // G: Ps[18][64] + E32[8][64] | anchors: Es[32][65]
    const int t = threadIdx.x;

    if (blockIdx.x == 0) {
        // ---- anchor projections -> g_C
        #pragma unroll
        for (int i = 0; i < 16; i++) {
            int idx = t + i * 256;
            int k = idx >> 6, d = idx & 63;
            Wt[k * 65 + d] = Wh[k * 2 * DDIM + d];             // W1[k][d]
        }
        float* Es = Buf;                                       // [32][65]
        #pragma unroll
        for (int i = 0; i < 8; i++) {
            int idx = t + i * 256;
            int a = idx >> 6, d = idx & 63;
            Es[a * 65 + d] = embeds[(size_t)anchor[a] * DDIM + d];
        }
        __syncthreads();
        int ia = t >> 3;
        int kbase = (t & 7) * 8;
        float s[8];
        #pragma unroll
        for (int kk = 0; kk < 8; kk++) s[kk] = 0.f;
        #pragma unroll 8
        for (int d = 0; d < DDIM; d++) {
            float e = Es[ia * 65 + d];
            #pragma unroll
            for (int kk = 0; kk < 8; kk++) s[kk] += e * Wt[(kbase + kk) * 65 + d];
        }
        #pragma unroll
        for (int kk = 0; kk < 8; kk++)
            g_C[ia * DDIM + kbase + kk] = s[kk] * (1.0f / 32.0f);
        return;
    }

    // ---- G path
    const int u0 = (blockIdx.x - 1) * UB;
    // stage W2 transposed: Wt[d*65+k] = Wh[k*128+64+d]
    #pragma unroll
    for (int i = 0; i < 4; i++) {
        int idx = t + i * 256;            // 1024 float4 tasks
        int k = idx >> 4, dq = idx & 15;
        float4 v = *(const float4*)(Wh + k * 2 * DDIM + DDIM + 4 * dq);
        Wt[(4 * dq + 0) * 65 + k] = v.x;
        Wt[(4 * dq + 1) * 65 + k] = v.y;
        Wt[(4 * dq + 2) * 65 + k] = v.z;
        Wt[(4 * dq + 3) * 65 + k] = v.w;
    }
    // phase A: 288 tasks of 8-row float4 partial sums (u's u0..u0+8)
    float* Ps = Buf;                      // [18][64]
    for (int s = t; s < (UB + 1) * 32; s += 256) {
        int uu = s >> 5, h = (s >> 4) & 1, c = s & 15;
        int rb = 16 * (u0 + uu);
        if (rb >= NTOT) rb -= NTOT;       // wrap (u = NG neighbor)
        const float4* src = (const float4*)(embeds + (size_t)(rb + 8 * h) * DDIM) + c;
        float4 a = make_float4(0.f, 0.f, 0.f, 0.f);
        #pragma unroll
        for (int j = 0; j < 8; j++) {
            float4 v = src[j * 16];
            a.x += v.x; a.y += v.y; a.z += v.z; a.w += v.w;
        }
        float* dst = Ps + (uu * 2 + h) * DDIM + 4 * c;
        dst[0] = a.x; dst[1] = a.y; dst[2] = a.z; dst[3] = a.w;
    }
    __syncthreads();
    // phase B: E32[uu][d] (512 tasks)
    float* E32 = Buf + 18 * DDIM;         // [8][64]
    #pragma unroll
    for (int i = 0; i < 2; i++) {
        int s = t + i * 256;
        int uu = s >> 6, d = s & 63;
        E32[uu * DDIM + d] =
            Ps[(2 * uu) * DDIM + d] + Ps[(2 * uu + 1) * DDIM + d] +
            Ps[(2 * uu + 2) * DDIM + d] + Ps[(2 * uu + 3) * DDIM + d];
    }
    __syncthreads();
    // phase C: 2 outputs/thread
    {
        int k = t & 63;
        int uu0 = t >> 6;                 // 0..3
        float b = __ldg(bias + k);
        #pragma unroll
        for (int ii = 0; ii < 2; ii++) {
            int uu = uu0 + 4 * ii;
            int u = u0 + uu;
            float s = 0.f;
            #pragma unroll 16
            for (int d = 0; d < DDIM; d++)
                s += E32[uu * DDIM + d] * Wt[d * 65 + k];   // broadcast x stride-1
            if (u < NG)
                g_G2[u * DDIM + k] = s * (1.0f / 32.0f) + b;
        }
    }
}

// ---------------------------------------------------------------------------
// main: block = 64 rows x 64 cols, 128 threads; warp = 64 rows x 16 cols.
// dists loaded to registers via asm-volatile BEFORE the PDL wait, so the
// whole dists DRAM read overlaps prep's execution.
// out[n,k] = sum_a dists[a,n]*C[a,k] + G2[(2n)%NG, k]
// ---------------------------------------------------------------------------
__global__ __launch_bounds__(128) void main_kernel(
    const float* __restrict__ dists,
    float* __restrict__ out)
{
    __shared__ __align__(16) float Cs[AANCH * DDIM];   // 8 KB
    __shared__ __align__(16) float Os[MROWS * 65];     // 16.25 KB
    const int t = threadIdx.x;
    const int lane = t & 31;
    const int wid = t >> 5;
    const int c0 = wid * 16;
    const int rowbase = blockIdx.x * MROWS;

    int n0 = rowbase + lane;      if (n0 >= NTOT) n0 = NTOT - 1;
    int n1 = rowbase + 32 + lane; if (n1 >= NTOT) n1 = NTOT - 1;

    // 64 forced-register DRAM loads, independent of prep — issue all now.
    float dv0[32], dv1[32];
    #pragma unroll
    for (int a = 0; a < 32; a++) dv0[a] = ldg_force(dists + (size_t)a * NTOT + n0);
    #pragma unroll
    for (int a = 0; a < 32; a++) dv1[a] = ldg_force(dists + (size_t)a * NTOT + n1);

    // wait for prep grid (g_C, g_G2 visible after this)
    asm volatile("griddepcontrol.wait;" ::: "memory");

    {   // stage C
        float4* dst = (float4*)Cs;
        const float4* src = (const float4*)g_C;
        #pragma unroll
        for (int i = 0; i < 4; i++)
            dst[t + i * 128] = src[t + i * 128];
    }
    __syncthreads();

    u64 acc0[8], acc1[8];
    #pragma unroll
    for (int q = 0; q < 8; q++) { acc0[q] = 0ULL; acc1[q] = 0ULL; }

    const float4* Crow = (const float4*)Cs + (c0 >> 2);
    #pragma unroll
    for (int a = 0; a < 32; a++) {
        u64 b0 = pack2(dv0[a], dv0[a]);
        u64 b1 = pack2(dv1[a], dv1[a]);
        #pragma unroll
        for (int qq = 0; qq < 4; qq++) {
            F4U cu; cu.f = Crow[a * 16 + qq];              // broadcast LDS.128
            acc0[2 * qq]     = fma2(b0, cu.u[0], acc0[2 * qq]);
            acc0[2 * qq + 1] = fma2(b0, cu.u[1], acc0[2 * qq + 1]);
            acc1[2 * qq]     = fma2(b1, cu.u[0], acc1[2 * qq]);
            acc1[2 * qq + 1] = fma2(b1, cu.u[1], acc1[2 * qq + 1]);
        }
    }

    // block transpose tile, scalar STS stride 65 (conflict-free)
    #pragma unroll
    for (int qq = 0; qq < 8; qq++) {
        float x, y;
        unpack2(acc0[qq], x, y);
        Os[lane * 65 + c0 + 2 * qq]     = x;
        Os[lane * 65 + c0 + 2 * qq + 1] = y;
        unpack2(acc1[qq], x, y);
        Os[(32 + lane) * 65 + c0 + 2 * qq]     = x;
        Os[(32 + lane) * 65 + c0 + 2 * qq + 1] = y;
    }
    __syncthreads();

    // fused G2 add + coalesced store (G2 is L2-resident, 32x reused)
    const int rows_valid = NTOT - rowbase;
    const int k = t & 63;
    int r = t >> 6;
    int u1 = (2 * (rowbase + r)) % NG;
    #pragma unroll 8
    for (int i = 0; i < MROWS / 2; i++, r += 2) {
        if (r < rows_valid) {
            float g = __ldg(g_G2 + (size_t)u1 * DDIM + k);
            out[(size_t)(rowbase + r) * DDIM + k] = Os[r * 65 + k] + g;
        }
        u1 += 4; if (u1 >= NG) u1 -= NG;
    }
}

// ---------------------------------------------------------------------------
extern "C" void kernel_launch(void* const* d_in, const int* in_sizes, int n_in,
                              void* d_out, int out_size)
{
    const float* embeds = (const float*)d_in[0];   // (N, D)
    const float* dists  = (const float*)d_in[1];   // (A, N)
    const int*   anchor = (const int*)d_in[2];     // (A,)
    const float* Wh     = (const float*)d_in[3];   // (D, 2D)
    const float* bias   = (const float*)d_in[4];   // (D,)
    float* out = (float*)d_out;
    (void)in_sizes; (void)n_in; (void)out_size;

    prep_kernel<<<NBG + 1, 256>>>(embeds, anchor, Wh, bias);

    // PDL: main launches early; its dists loads overlap prep's tail.
    cudaLaunchConfig_t cfg = {};
    cfg.gridDim  = dim3((NTOT + MROWS - 1) / MROWS);   // 782
    cfg.blockDim = dim3(128);
    cudaLaunchAttribute attr[1];
    attr[0].id = cudaLaunchAttributeProgrammaticStreamSerialization;
    attr[0].val.programmaticStreamSerializationAllowed = 1;
    cfg.attrs = attr;
    cfg.numAttrs = 1;
    cudaLaunchKernelEx(&cfg, main_kernel, dists, out);
}